// round 9
// baseline (speedup 1.0000x reference)
#include <cuda_runtime.h>
#include <cuda_bf16.h>
#include <math.h>

#define BATCH 8
#define SEQ   8192
#define DIM   512
#define HEADS 8
#define DH    64
#define SL    32
#define MTOT  (BATCH * SEQ)
#define NSPLIT 128                 // 64 tokens per split
#define QDIM  (HEADS * SL)         // 256

// ---------------- device scratch ----------------
__device__ float g_xmid[(size_t)MTOT * DIM];
__device__ float g_q   [(size_t)MTOT * QDIM];
__device__ float g_S1p [(size_t)NSPLIT * 64 * SL * DH];
__device__ float g_S0p [(size_t)NSPLIT * 64 * SL];
__device__ float g_kv  [(size_t)64 * SL * DH];
__device__ float g_Z   [(size_t)BATCH * QDIM * DIM];
__device__ float g_Wr  [(size_t)DIM * DIM];            // rna-rounded W_in

__device__ __forceinline__ unsigned f2tf32(float f) {
    unsigned u;
    asm("cvt.rna.tf32.f32 %0, %1;" : "=r"(u) : "f"(f));
    return u;
}
__device__ __forceinline__ float tf32r(float f) { return __uint_as_float(f2tf32(f)); }
__device__ __forceinline__ float4 tf32r4(float4 v) {
    float4 o; o.x = tf32r(v.x); o.y = tf32r(v.y); o.z = tf32r(v.z); o.w = tf32r(v.w);
    return o;
}
__device__ __forceinline__ void mma_tf32(float* c, const unsigned* a, const unsigned* b) {
    asm volatile(
        "mma.sync.aligned.m16n8k8.row.col.f32.tf32.tf32.f32 "
        "{%0,%1,%2,%3}, {%4,%5,%6,%7}, {%8,%9}, {%0,%1,%2,%3};"
        : "+f"(c[0]), "+f"(c[1]), "+f"(c[2]), "+f"(c[3])
        : "r"(a[0]), "r"(a[1]), "r"(a[2]), "r"(a[3]), "r"(b[0]), "r"(b[1]));
}
__device__ __forceinline__ unsigned smem_u32(const void* p) {
    return (unsigned)__cvta_generic_to_shared(p);
}
#define CP16(dst, src) asm volatile("cp.async.cg.shared.global [%0], [%1], 16;" :: "r"(dst), "l"(src))
#define CP_COMMIT()    asm volatile("cp.async.commit_group;")
#define CP_WAIT1()     asm volatile("cp.async.wait_group 1;")
#define CP_WAIT0()     asm volatile("cp.async.wait_group 0;")

// ---------------- elementwise rna pre-round ----------------
__global__ __launch_bounds__(256) void round_kernel(
    const float* __restrict__ in, float* __restrict__ out, int n)
{
    int i = blockIdx.x * 256 + threadIdx.x;
    if (i < n) out[i] = tf32r(in[i]);
}

// ---------------- TF32 GEMM, 128x128 tile, BK=16, cp.async 2-stage ----------------
// RA/RB: apply rna tf32 rounding to A/B fragments (false => input pre-rounded, HW-truncate OK)
template<bool RA, bool RB>
__global__ __launch_bounds__(256) void tf32gemm_bias_kernel(
    const float* __restrict__ A, const float* __restrict__ W,
    const float* __restrict__ bias, float* __restrict__ C, int K,
    size_t zStrideA, size_t zStrideW, size_t zStrideC)
{
    const int N = 512;
    __shared__ float As[2][128][20];
    __shared__ float Bs[2][16][136];

    const int tid  = threadIdx.x;
    const int warp = tid >> 5;
    const int lane = tid & 31;
    const int g = lane >> 2;
    const int t = lane & 3;

    const int rowBase = blockIdx.y * 128;
    const int colBase = blockIdx.x * 128;
    const int wm = (warp & 3) * 32;
    const int wn = (warp >> 2) * 64;

    A += zStrideA * blockIdx.z;
    W += zStrideW * blockIdx.z;
    C += zStrideC * blockIdx.z;

    float acc[2][8][4];
#pragma unroll
    for (int mt = 0; mt < 2; mt++)
#pragma unroll
        for (int nt = 0; nt < 8; nt++)
#pragma unroll
            for (int i = 0; i < 4; i++) acc[mt][nt][i] = 0.f;

    const int aRow = tid >> 2;
    const int aC4  = (tid & 3) * 4;
    const int bRow = tid >> 5;
    const int bC4  = (tid & 31) * 4;

    const float* Ag  = A + (size_t)(rowBase + aRow) * K + aC4;
    const float* Ag2 = Ag + (size_t)64 * K;
    const float* Bg  = W + (size_t)bRow * N + colBase + bC4;
    const float* Bg2 = Bg + (size_t)8 * N;

    unsigned sA0 = smem_u32(&As[0][aRow][aC4]);
    unsigned sA1 = smem_u32(&As[0][aRow + 64][aC4]);
    unsigned sB0 = smem_u32(&Bs[0][bRow][bC4]);
    unsigned sB1 = smem_u32(&Bs[0][bRow + 8][bC4]);
    const unsigned strideA = 128 * 20 * 4;
    const unsigned strideB = 16 * 136 * 4;

    CP16(sA0, Ag);  CP16(sA1, Ag2);
    CP16(sB0, Bg);  CP16(sB1, Bg2);
    CP_COMMIT();

    const int nIter = K >> 4;
#pragma unroll 1
    for (int it = 0; it < nIter; it++) {
        const int kt = it * 16;
        const int cur = it & 1;
        if (it + 1 < nIter) {
            const unsigned off  = (cur ^ 1) ? strideA : 0;
            const unsigned offB = (cur ^ 1) ? strideB : 0;
            CP16(sA0 + off, Ag + kt + 16);
            CP16(sA1 + off, Ag2 + kt + 16);
            CP16(sB0 + offB, Bg + (size_t)(kt + 16) * N);
            CP16(sB1 + offB, Bg2 + (size_t)(kt + 16) * N);
            CP_COMMIT();
            CP_WAIT1();
        } else {
            CP_WAIT0();
        }
        __syncthreads();

#pragma unroll
        for (int ks = 0; ks < 16; ks += 8) {
            unsigned af[2][4], bf[8][2];
#pragma unroll
            for (int mt = 0; mt < 2; mt++) {
                const int r0 = wm + mt * 16 + g;
                if (RA) {
                    af[mt][0] = f2tf32(As[cur][r0    ][ks + t    ]);
                    af[mt][1] = f2tf32(As[cur][r0 + 8][ks + t    ]);
                    af[mt][2] = f2tf32(As[cur][r0    ][ks + t + 4]);
                    af[mt][3] = f2tf32(As[cur][r0 + 8][ks + t + 4]);
                } else {
                    af[mt][0] = __float_as_uint(As[cur][r0    ][ks + t    ]);
                    af[mt][1] = __float_as_uint(As[cur][r0 + 8][ks + t    ]);
                    af[mt][2] = __float_as_uint(As[cur][r0    ][ks + t + 4]);
                    af[mt][3] = __float_as_uint(As[cur][r0 + 8][ks + t + 4]);
                }
            }
#pragma unroll
            for (int nt = 0; nt < 8; nt++) {
                const int c0 = wn + nt * 8 + g;
                if (RB) {
                    bf[nt][0] = f2tf32(Bs[cur][ks + t    ][c0]);
                    bf[nt][1] = f2tf32(Bs[cur][ks + t + 4][c0]);
                } else {
                    bf[nt][0] = __float_as_uint(Bs[cur][ks + t    ][c0]);
                    bf[nt][1] = __float_as_uint(Bs[cur][ks + t + 4][c0]);
                }
            }
#pragma unroll
            for (int mt = 0; mt < 2; mt++)
#pragma unroll
                for (int nt = 0; nt < 8; nt++)
                    mma_tf32(acc[mt][nt], af[mt], bf[nt]);
        }
        __syncthreads();
    }

#pragma unroll
    for (int nt = 0; nt < 8; nt++) {
        const int col = colBase + wn + nt * 8 + 2 * t;
        const float bx = bias[col], by = bias[col + 1];
#pragma unroll
        for (int mt = 0; mt < 2; mt++) {
            const int row0 = rowBase + wm + mt * 16 + g;
            float2 o0, o1;
            o0.x = acc[mt][nt][0] + bx; o0.y = acc[mt][nt][1] + by;
            o1.x = acc[mt][nt][2] + bx; o1.y = acc[mt][nt][3] + by;
            *reinterpret_cast<float2*>(&C[(size_t)row0 * N + col])       = o0;
            *reinterpret_cast<float2*>(&C[(size_t)(row0 + 8) * N + col]) = o1;
        }
    }
}

// ---------------- Fused kv + q kernel: 256 threads, 8 warps, no reg-cached weights -------------
// grid (NSPLIT, HEADS, BATCH). Warp (wr=w>>2, wc=w&3): proj block rows [32wr,+32) x cols [32wc,+32).
// SMEM: Xs[64][68] | union{ Ws[64][136] --> Es[32][68] + Vs[64][72] + Qs[64][36] }
#define KVQ_SMEM ((64*68 + 32*68 + 64*72 + 64*36) * 4)   // 53760 bytes

__global__ __launch_bounds__(256, 2) void kvq_fused_kernel(
    const float* __restrict__ xmid, const float* __restrict__ Wq,
    const float* __restrict__ Wk, const float* __restrict__ Wv)
{
    extern __shared__ float sm[];
    float* Xs = sm;                  // [64][68]
    float* Ws = sm + 64 * 68;        // [64][136] (transient)
    float* Es = sm + 64 * 68;        // [32][68]  (aliases Ws)
    float* Vs = Es + 32 * 68;        // [64][72]
    float* Qs = Vs + 64 * 72;        // [64][36]

    const int split = blockIdx.x;
    const int h = blockIdx.y;
    const int b = blockIdx.z;
    const int bh = b * HEADS + h;
    const int tid = threadIdx.x;
    const int w = tid >> 5;
    const int lane = tid & 31;
    const int g = lane >> 2;
    const int t = lane & 3;
    const int wr = w >> 2;           // 0..1 row half
    const int wc = w & 3;            // 0..3 col quarter
    const int n0 = split * 64;

    // loads: weights (transient, rounded) + X tile (rounded)
    for (int idx = tid; idx < 64 * 32; idx += 256) Ws[(idx >> 5) * 136 + (idx & 31)]      = tf32r(Wq[idx]);
    for (int idx = tid; idx < 64 * 32; idx += 256) Ws[(idx >> 5) * 136 + 32 + (idx & 31)] = tf32r(Wk[idx]);
    for (int idx = tid; idx < 64 * 64; idx += 256) Ws[(idx >> 6) * 136 + 64 + (idx & 63)] = tf32r(Wv[idx]);
    for (int idx = tid; idx < 64 * 16; idx += 256) {
        int r = idx >> 4, c4 = (idx & 15) * 4;
        float4 v = *reinterpret_cast<const float4*>(
            &xmid[(size_t)(b * SEQ + n0 + r) * DIM + h * DH + c4]);
        *reinterpret_cast<float4*>(&Xs[r * 68 + c4]) = tf32r4(v);
    }
    __syncthreads();

    // projection mma: warp block 32x32 = 2 mt x 4 nt, k=64; weights read from smem per step
    float pacc[2][4][4];
#pragma unroll
    for (int mt = 0; mt < 2; mt++)
#pragma unroll
        for (int nt = 0; nt < 4; nt++)
#pragma unroll
            for (int i = 0; i < 4; i++) pacc[mt][nt][i] = 0.f;

#pragma unroll
    for (int ks = 0; ks < 8; ks++) {
        unsigned af[2][4];
#pragma unroll
        for (int mt = 0; mt < 2; mt++) {
            const int r0 = 32 * wr + mt * 16 + g;
            af[mt][0] = __float_as_uint(Xs[(r0    ) * 68 + 8 * ks + t    ]);
            af[mt][1] = __float_as_uint(Xs[(r0 + 8) * 68 + 8 * ks + t    ]);
            af[mt][2] = __float_as_uint(Xs[(r0    ) * 68 + 8 * ks + t + 4]);
            af[mt][3] = __float_as_uint(Xs[(r0 + 8) * 68 + 8 * ks + t + 4]);
        }
#pragma unroll
        for (int nt = 0; nt < 4; nt++) {
            const int c0 = 32 * wc + nt * 8 + g;
            unsigned bf[2];
            bf[0] = __float_as_uint(Ws[(8 * ks + t    ) * 136 + c0]);
            bf[1] = __float_as_uint(Ws[(8 * ks + t + 4) * 136 + c0]);
#pragma unroll
            for (int mt = 0; mt < 2; mt++)
                mma_tf32(pacc[mt][nt], af[mt], bf);
        }
    }
    __syncthreads();   // all Ws reads complete -> union region reusable

    // epilogue by warp column-quarter
#pragma unroll
    for (int mt = 0; mt < 2; mt++)
#pragma unroll
        for (int nt = 0; nt < 4; nt++) {
            const int c0 = 32 * wc + nt * 8 + 2 * t;
            const int r0 = 32 * wr + mt * 16 + g;
            float v0 = pacc[mt][nt][0], v1 = pacc[mt][nt][1];
            float v2 = pacc[mt][nt][2], v3 = pacc[mt][nt][3];
            if (wc == 0) {                      // Q raw
                Qs[(r0    ) * 36 + c0]     = v0;
                Qs[(r0    ) * 36 + c0 + 1] = v1;
                Qs[(r0 + 8) * 36 + c0]     = v2;
                Qs[(r0 + 8) * 36 + c0 + 1] = v3;
            } else if (wc == 1) {               // E = exp(K), transposed [slice][token]
                const int s = c0 - 32;
                Es[(s    ) * 68 + r0]     = tf32r(expf(v0));
                Es[(s + 1) * 68 + r0]     = tf32r(expf(v1));
                Es[(s    ) * 68 + r0 + 8] = tf32r(expf(v2));
                Es[(s + 1) * 68 + r0 + 8] = tf32r(expf(v3));
            } else {                            // V [token][channel]
                const int c = c0 - 64;
                Vs[(r0    ) * 72 + c]     = tf32r(v0);
                Vs[(r0    ) * 72 + c + 1] = tf32r(v1);
                Vs[(r0 + 8) * 72 + c]     = tf32r(v2);
                Vs[(r0 + 8) * 72 + c + 1] = tf32r(v3);
            }
        }
    __syncthreads();

    // softmax over slice dim (one token per thread) + S0 column sums
    float s0val = 0.f;
    if (tid < 64) {
        float m = Qs[tid * 36 + 0];
#pragma unroll
        for (int s = 1; s < 32; s++) m = fmaxf(m, Qs[tid * 36 + s]);
        float e[32], sum = 0.f;
#pragma unroll
        for (int s = 0; s < 32; s++) { e[s] = expf(Qs[tid * 36 + s] - m); sum += e[s]; }
        float inv = 1.f / sum;
#pragma unroll
        for (int s = 0; s < 32; s++) Qs[tid * 36 + s] = e[s] * inv;
    } else if (tid < 96) {
        const int s = tid - 64;
#pragma unroll
        for (int r = 0; r < 64; r++) s0val += Es[s * 68 + r];
    }
    __syncthreads();

    // coalesced store of softmaxed Q, rna-rounded (GEMM2 consumes without rounding)
    for (int idx = tid; idx < 64 * 8; idx += 256) {
        int r = idx >> 3, c4 = (idx & 7) * 4;
        float4 v = *reinterpret_cast<const float4*>(&Qs[r * 36 + c4]);
        *reinterpret_cast<float4*>(
            &g_q[(size_t)(b * SEQ + n0 + r) * QDIM + h * SL + c4]) = tf32r4(v);
    }

    // S1 = Es(32x64tok) @ Vs(64tok x 64); warp: rows [16wr,+16) x cols [16wc,+16) (2 nt)
    float accS1[2][4];
#pragma unroll
    for (int nt = 0; nt < 2; nt++)
#pragma unroll
        for (int i = 0; i < 4; i++) accS1[nt][i] = 0.f;

#pragma unroll
    for (int ks = 0; ks < 8; ks++) {
        unsigned af2[4];
        const int r0 = 16 * wr + g;
        af2[0] = __float_as_uint(Es[(r0    ) * 68 + 8 * ks + t    ]);
        af2[1] = __float_as_uint(Es[(r0 + 8) * 68 + 8 * ks + t    ]);
        af2[2] = __float_as_uint(Es[(r0    ) * 68 + 8 * ks + t + 4]);
        af2[3] = __float_as_uint(Es[(r0 + 8) * 68 + 8 * ks + t + 4]);
#pragma unroll
        for (int nt = 0; nt < 2; nt++) {
            const int c0 = 16 * wc + nt * 8 + g;
            unsigned bf2[2];
            bf2[0] = __float_as_uint(Vs[(8 * ks + t    ) * 72 + c0]);
            bf2[1] = __float_as_uint(Vs[(8 * ks + t + 4) * 72 + c0]);
            mma_tf32(accS1[nt], af2, bf2);
        }
    }

    // write per-split partials
    float* base = g_S1p + ((size_t)split * 64 + bh) * (SL * DH);
#pragma unroll
    for (int nt = 0; nt < 2; nt++) {
        const int s0 = 16 * wr + g;
        const int c  = 16 * wc + nt * 8 + 2 * t;
        base[(s0    ) * DH + c]     = accS1[nt][0];
        base[(s0    ) * DH + c + 1] = accS1[nt][1];
        base[(s0 + 8) * DH + c]     = accS1[nt][2];
        base[(s0 + 8) * DH + c + 1] = accS1[nt][3];
    }
    if (tid >= 64 && tid < 96)
        g_S0p[((size_t)split * 64 + bh) * SL + (tid - 64)] = s0val;
}

// ---------------- kv finalize ----------------
__global__ __launch_bounds__(256) void kv_final_kernel()
{
    int idx = blockIdx.x * 256 + threadIdx.x;
    if (idx >= 64 * SL * DH) return;
    int bh = idx >> 11;
    int sc = idx & 2047;
    int s  = sc >> 6;
    float s1 = 0.f, s0 = 0.f;
    for (int sp = 0; sp < NSPLIT; sp++) {
        s1 += g_S1p[((size_t)sp * 64 + bh) * (SL * DH) + sc];
        s0 += g_S0p[((size_t)sp * 64 + bh) * SL + s];
    }
    g_kv[idx] = s1 / s0;
}

// ---------------- Z prep: Z[b][h*32+s][:] = kv[b,h] @ W_out[h*64:(h+1)*64, :], rna-rounded ------
__global__ __launch_bounds__(256) void zprep_kernel(const float* __restrict__ W_out)
{
    const int cb = blockIdx.x;
    const int h  = blockIdx.y;
    const int b  = blockIdx.z;
    const int bh = b * HEADS + h;
    const int tid = threadIdx.x;

    __shared__ float kvs[32][64];
    __shared__ float Wos[64][64];

    for (int idx = tid; idx < SL * DH; idx += 256)
        kvs[idx >> 6][idx & 63] = g_kv[(size_t)bh * (SL * DH) + idx];
    for (int idx = tid; idx < 64 * 64; idx += 256) {
        int r = idx >> 6, c = idx & 63;
        Wos[r][c] = W_out[(size_t)(h * DH + r) * DIM + cb * 64 + c];
    }
    __syncthreads();

    for (int idx = tid; idx < SL * 64; idx += 256) {
        int s = idx >> 6, c = idx & 63;
        float d = 0.f;
#pragma unroll
        for (int k = 0; k < 64; k++) d = fmaf(kvs[s][k], Wos[k][c], d);
        g_Z[((size_t)b * QDIM + h * SL + s) * DIM + cb * 64 + c] = tf32r(d);
    }
}

// ---------------- launch ----------------
extern "C" void kernel_launch(void* const* d_in, const int* in_sizes, int n_in,
                              void* d_out, int out_size)
{
    const float* x     = (const float*)d_in[0];
    const float* W_in  = (const float*)d_in[1];
    const float* b_in  = (const float*)d_in[2];
    const float* Wq    = (const float*)d_in[3];
    const float* Wk    = (const float*)d_in[4];
    const float* Wv    = (const float*)d_in[5];
    const float* W_out = (const float*)d_in[6];
    const float* b_out = (const float*)d_in[7];
    float* out = (float*)d_out;

    float *xmid, *q, *Z, *Wr;
    cudaGetSymbolAddress((void**)&xmid, g_xmid);
    cudaGetSymbolAddress((void**)&q, g_q);
    cudaGetSymbolAddress((void**)&Z, g_Z);
    cudaGetSymbolAddress((void**)&Wr, g_Wr);

    cudaFuncSetAttribute(kvq_fused_kernel,
                         cudaFuncAttributeMaxDynamicSharedMemorySize, KVQ_SMEM);

    // 0) pre-round W_in (rna) so GEMM1 skips B-side cvt
    round_kernel<<<(DIM * DIM + 255) / 256, 256>>>(W_in, Wr, DIM * DIM);

    // 1) x_mid = x @ W_in + b_in   (K=512; round A on load, B pre-rounded)
    dim3 g1(DIM / 128, MTOT / 128, 1);
    tf32gemm_bias_kernel<true, false><<<g1, 256>>>(x, Wr, b_in, xmid, DIM, 0, 0, 0);

    // 2) fused: q-softmax -> g_q (pre-rounded), kv split partials
    dim3 kvGrid(NSPLIT, HEADS, BATCH);
    kvq_fused_kernel<<<kvGrid, 256, KVQ_SMEM>>>(xmid, Wq, Wk, Wv);

    // 3) kv finalize
    kv_final_kernel<<<(64 * SL * DH + 255) / 256, 256>>>();

    // 4) Z = kv @ W_out (pre-rounded)
    dim3 zGrid(DIM / 64, HEADS, BATCH);
    zprep_kernel<<<zGrid, 256>>>(W_out);

    // 5) out = Q @ Z_b + b_out    (K=256, batched; both operands pre-rounded)
    dim3 g2(DIM / 128, SEQ / 128, BATCH);
    tf32gemm_bias_kernel<false, false><<<g2, 256>>>(q, Z, b_out, out, QDIM,
                                                    (size_t)SEQ * QDIM,
                                                    (size_t)QDIM * DIM,
                                                    (size_t)SEQ * DIM);
}

// round 11
// speedup vs baseline: 1.2392x; 1.2392x over previous
#include <cuda_runtime.h>
#include <cuda_fp16.h>
#include <math.h>

#define BATCH 8
#define SEQ   8192
#define DIM   512
#define HEADS 8
#define DH    64
#define SL    32
#define MTOT  (BATCH * SEQ)
#define KV_SPLITS 64
#define QDIM  (HEADS * SL)        // 256

// ---------------- device scratch ----------------
__device__ float  g_xmid[(size_t)MTOT * DIM];
__device__ __half g_xh  [(size_t)MTOT * DIM];          // fp16 copy of x
__device__ __half g_qh  [(size_t)MTOT * QDIM];         // softmaxed Q, fp16
__device__ float  g_S1p [(size_t)KV_SPLITS * 64 * SL * DH];
__device__ float  g_S0p [(size_t)KV_SPLITS * 64 * SL];
__device__ float  g_kv  [(size_t)64 * SL * DH];
__device__ __half g_Wp  [(size_t)DIM * DIM];           // W_in in k-paired fp16 layout
__device__ __half g_Zp  [(size_t)BATCH * QDIM * DIM];  // Z per batch, k-paired fp16 layout

__device__ __forceinline__ unsigned f2tf32(float f) {
    unsigned u;
    asm("cvt.rna.tf32.f32 %0, %1;" : "=r"(u) : "f"(f));
    return u;
}
__device__ __forceinline__ float tf32r(float f) { return __uint_as_float(f2tf32(f)); }
__device__ __forceinline__ float4 tf32r4(float4 v) {
    float4 o; o.x = tf32r(v.x); o.y = tf32r(v.y); o.z = tf32r(v.z); o.w = tf32r(v.w);
    return o;
}
__device__ __forceinline__ void mma_tf32(float* c, const unsigned* a, const unsigned* b) {
    asm volatile(
        "mma.sync.aligned.m16n8k8.row.col.f32.tf32.tf32.f32 "
        "{%0,%1,%2,%3}, {%4,%5,%6,%7}, {%8,%9}, {%0,%1,%2,%3};"
        : "+f"(c[0]), "+f"(c[1]), "+f"(c[2]), "+f"(c[3])
        : "r"(a[0]), "r"(a[1]), "r"(a[2]), "r"(a[3]), "r"(b[0]), "r"(b[1]));
}
__device__ __forceinline__ void mma_f16(float* c, const unsigned* a, const unsigned* b) {
    asm volatile(
        "mma.sync.aligned.m16n8k16.row.col.f32.f16.f16.f32 "
        "{%0,%1,%2,%3}, {%4,%5,%6,%7}, {%8,%9}, {%0,%1,%2,%3};"
        : "+f"(c[0]), "+f"(c[1]), "+f"(c[2]), "+f"(c[3])
        : "r"(a[0]), "r"(a[1]), "r"(a[2]), "r"(a[3]), "r"(b[0]), "r"(b[1]));
}
__device__ __forceinline__ unsigned smem_u32(const void* p) {
    return (unsigned)__cvta_generic_to_shared(p);
}
#define CP16(dst, src) asm volatile("cp.async.cg.shared.global [%0], [%1], 16;" :: "r"(dst), "l"(src))
#define CP_COMMIT()    asm volatile("cp.async.commit_group;")
#define CP_WAIT1()     asm volatile("cp.async.wait_group 1;")
#define CP_WAIT0()     asm volatile("cp.async.wait_group 0;")

// ---------------- fp32 -> fp16 bulk convert (vectorized) ----------------
__global__ __launch_bounds__(256) void f2h_kernel(
    const float4* __restrict__ in, uint2* __restrict__ out, int n4)
{
    int i = blockIdx.x * 256 + threadIdx.x;
    if (i >= n4) return;
    float4 v = in[i];
    __half2 h0 = __floats2half2_rn(v.x, v.y);
    __half2 h1 = __floats2half2_rn(v.z, v.w);
    uint2 o;
    o.x = *reinterpret_cast<unsigned*>(&h0);
    o.y = *reinterpret_cast<unsigned*>(&h1);
    out[i] = o;
}

// ---------------- W -> k-paired fp16 layout: Wp[((k>>1)*N + n)*2 + (k&1)] = h(W[k][n]) --------
__global__ __launch_bounds__(256) void wpair_kernel(
    const float* __restrict__ W, __half* __restrict__ Wp, int K, int N)
{
    int idx = blockIdx.x * 256 + threadIdx.x;
    if (idx >= K * N) return;
    int k = idx / N, n = idx - k * N;
    Wp[((size_t)(k >> 1) * N + n) * 2 + (k & 1)] = __float2half(W[idx]);
}

// ---------------- FP16 GEMM: C[M,512] = A[M,K](h) @ B[K,512](paired h) + bias(f32) ------------
// 128x128 tile, BK=16, cp.async 2-stage, 256 threads, warp tile 32x64 (2mt x 8nt m16n8k16).
__global__ __launch_bounds__(256) void h16gemm_bias_kernel(
    const __half* __restrict__ A, const __half2* __restrict__ Bp,
    const float* __restrict__ bias, float* __restrict__ C, int K,
    size_t zStrideA, size_t zStrideB, size_t zStrideC)
{
    const int N = 512;
    __shared__ __half  As[2][128][24];   // 16 used/row; word stride 12 -> (12g+t)%32 distinct
    __shared__ __half2 Bs[2][8][136];    // k-pairs x n; word stride 136 -> (8t+g)%32 distinct

    const int tid  = threadIdx.x;
    const int warp = tid >> 5;
    const int lane = tid & 31;
    const int g = lane >> 2;
    const int t = lane & 3;

    const int rowBase = blockIdx.y * 128;
    const int colBase = blockIdx.x * 128;
    const int wm = (warp & 3) * 32;
    const int wn = (warp >> 2) * 64;

    A  += zStrideA * blockIdx.z;
    Bp += zStrideB * blockIdx.z;
    C  += zStrideC * blockIdx.z;

    float acc[2][8][4];
#pragma unroll
    for (int mt = 0; mt < 2; mt++)
#pragma unroll
        for (int nt = 0; nt < 8; nt++)
#pragma unroll
            for (int i = 0; i < 4; i++) acc[mt][nt][i] = 0.f;

    // cp.async mapping: A tile 128x16 halves = 4KB; B tile 8x128 half2 = 4KB
    const int aRow = tid >> 1;            // 0..127
    const int aOff = (tid & 1) * 8;       // half offset 0 or 8
    const int bKK  = tid >> 5;            // 0..7 k-pair row
    const int bN4  = (tid & 31) * 4;      // half2 col, 4 per thread

    const __half*  Ag = A + (size_t)(rowBase + aRow) * K + aOff;
    const __half2* Bg = Bp + (size_t)bKK * N + colBase + bN4;

    unsigned sA = smem_u32(&As[0][aRow][aOff]);
    unsigned sB = smem_u32(&Bs[0][bKK][bN4]);
    const unsigned strideA = 128 * 24 * 2;   // bytes per A stage
    const unsigned strideB = 8 * 136 * 4;    // bytes per B stage

    CP16(sA, Ag);
    CP16(sB, Bg);
    CP_COMMIT();

    const int nIter = K >> 4;
#pragma unroll 1
    for (int it = 0; it < nIter; it++) {
        const int kt = it * 16;
        const int cur = it & 1;
        if (it + 1 < nIter) {
            const unsigned offA = (cur ^ 1) ? strideA : 0;
            const unsigned offB = (cur ^ 1) ? strideB : 0;
            CP16(sA + offA, Ag + kt + 16);
            CP16(sB + offB, Bg + (size_t)(it + 1) * 8 * N);   // tile it+1: k-pairs [8(it+1), 8(it+2))
            CP_COMMIT();
            CP_WAIT1();
        } else {
            CP_WAIT0();
        }
        __syncthreads();

        unsigned af[2][4], bf[8][2];
#pragma unroll
        for (int mt = 0; mt < 2; mt++) {
            const int r0 = wm + mt * 16 + g;
            af[mt][0] = *reinterpret_cast<const unsigned*>(&As[cur][r0    ][2 * t    ]);
            af[mt][1] = *reinterpret_cast<const unsigned*>(&As[cur][r0 + 8][2 * t    ]);
            af[mt][2] = *reinterpret_cast<const unsigned*>(&As[cur][r0    ][2 * t + 8]);
            af[mt][3] = *reinterpret_cast<const unsigned*>(&As[cur][r0 + 8][2 * t + 8]);
        }
#pragma unroll
        for (int nt = 0; nt < 8; nt++) {
            const int c0 = wn + nt * 8 + g;
            bf[nt][0] = *reinterpret_cast<const unsigned*>(&Bs[cur][t    ][c0]);
            bf[nt][1] = *reinterpret_cast<const unsigned*>(&Bs[cur][t + 4][c0]);
        }
#pragma unroll
        for (int mt = 0; mt < 2; mt++)
#pragma unroll
            for (int nt = 0; nt < 8; nt++)
                mma_f16(acc[mt][nt], af[mt], bf[nt]);
        __syncthreads();
    }

#pragma unroll
    for (int nt = 0; nt < 8; nt++) {
        const int col = colBase + wn + nt * 8 + 2 * t;
        const float bx = bias[col], by = bias[col + 1];
#pragma unroll
        for (int mt = 0; mt < 2; mt++) {
            const int row0 = rowBase + wm + mt * 16 + g;
            float2 o0, o1;
            o0.x = acc[mt][nt][0] + bx; o0.y = acc[mt][nt][1] + by;
            o1.x = acc[mt][nt][2] + bx; o1.y = acc[mt][nt][3] + by;
            *reinterpret_cast<float2*>(&C[(size_t)row0 * N + col])       = o0;
            *reinterpret_cast<float2*>(&C[(size_t)(row0 + 8) * N + col]) = o1;
        }
    }
}

// ---------------- Fused kv + q kernel (round-6 proven; only Q store changed to fp16) ----------
__global__ __launch_bounds__(128) void kvq_fused_kernel(
    const float* __restrict__ xmid, const float* __restrict__ Wq,
    const float* __restrict__ Wk, const float* __restrict__ Wv)
{
    const int split = blockIdx.x;
    const int h = blockIdx.y;
    const int b = blockIdx.z;
    const int bh = b * HEADS + h;
    const int tid = threadIdx.x;
    const int w = tid >> 5;
    const int lane = tid & 31;
    const int g = lane >> 2;
    const int t = lane & 3;

    __shared__ float Ws[64][136];
    __shared__ float Xs[64][68];
    __shared__ float Es[32][68];
    __shared__ float Vs[64][72];
    __shared__ float Qs[64][36];

    for (int idx = tid; idx < 64 * 32; idx += 128) Ws[idx >> 5][idx & 31]        = tf32r(Wq[idx]);
    for (int idx = tid; idx < 64 * 32; idx += 128) Ws[idx >> 5][32 + (idx & 31)] = tf32r(Wk[idx]);
    for (int idx = tid; idx < 64 * 64; idx += 128) Ws[idx >> 6][64 + (idx & 63)] = tf32r(Wv[idx]);
    __syncthreads();

    unsigned bfw[4][8][2];
#pragma unroll
    for (int nt = 0; nt < 4; nt++)
#pragma unroll
        for (int ks = 0; ks < 8; ks++) {
            const int c0 = 32 * w + nt * 8 + g;
            bfw[nt][ks][0] = __float_as_uint(Ws[8 * ks + t    ][c0]);
            bfw[nt][ks][1] = __float_as_uint(Ws[8 * ks + t + 4][c0]);
        }

    float accS1[2][2][4];
#pragma unroll
    for (int mt = 0; mt < 2; mt++)
#pragma unroll
        for (int nt = 0; nt < 2; nt++)
#pragma unroll
            for (int i = 0; i < 4; i++) accS1[mt][nt][i] = 0.f;
    float s0acc = 0.f;

#pragma unroll 1
    for (int chunk = 0; chunk < 2; chunk++) {
        const int n0 = split * 128 + chunk * 64;
        __syncthreads();

        for (int idx = tid; idx < 64 * 16; idx += 128) {
            int r = idx >> 4, c4 = (idx & 15) * 4;
            float4 v = *reinterpret_cast<const float4*>(
                &xmid[(size_t)(b * SEQ + n0 + r) * DIM + h * DH + c4]);
            *reinterpret_cast<float4*>(&Xs[r][c4]) = tf32r4(v);
        }
        __syncthreads();

        float pacc[4][4][4];
#pragma unroll
        for (int mt = 0; mt < 4; mt++)
#pragma unroll
            for (int nt = 0; nt < 4; nt++)
#pragma unroll
                for (int i = 0; i < 4; i++) pacc[mt][nt][i] = 0.f;

#pragma unroll
        for (int ks = 0; ks < 8; ks++) {
            unsigned af[4][4];
#pragma unroll
            for (int mt = 0; mt < 4; mt++) {
                const int r0 = mt * 16 + g;
                af[mt][0] = __float_as_uint(Xs[r0    ][8 * ks + t    ]);
                af[mt][1] = __float_as_uint(Xs[r0 + 8][8 * ks + t    ]);
                af[mt][2] = __float_as_uint(Xs[r0    ][8 * ks + t + 4]);
                af[mt][3] = __float_as_uint(Xs[r0 + 8][8 * ks + t + 4]);
            }
#pragma unroll
            for (int mt = 0; mt < 4; mt++)
#pragma unroll
                for (int nt = 0; nt < 4; nt++)
                    mma_tf32(pacc[mt][nt], af[mt], bfw[nt][ks]);
        }

#pragma unroll
        for (int mt = 0; mt < 4; mt++)
#pragma unroll
            for (int nt = 0; nt < 4; nt++) {
                const int c0 = 32 * w + nt * 8 + 2 * t;
                const int r0 = mt * 16 + g;
                float v0 = pacc[mt][nt][0], v1 = pacc[mt][nt][1];
                float v2 = pacc[mt][nt][2], v3 = pacc[mt][nt][3];
                if (w == 0) {
                    Qs[r0    ][c0]     = v0;
                    Qs[r0    ][c0 + 1] = v1;
                    Qs[r0 + 8][c0]     = v2;
                    Qs[r0 + 8][c0 + 1] = v3;
                } else if (w == 1) {
                    const int s = c0 - 32;
                    Es[s    ][r0]     = tf32r(expf(v0));
                    Es[s + 1][r0]     = tf32r(expf(v1));
                    Es[s    ][r0 + 8] = tf32r(expf(v2));
                    Es[s + 1][r0 + 8] = tf32r(expf(v3));
                } else {
                    const int c = c0 - 64;
                    Vs[r0    ][c]     = tf32r(v0);
                    Vs[r0    ][c + 1] = tf32r(v1);
                    Vs[r0 + 8][c]     = tf32r(v2);
                    Vs[r0 + 8][c + 1] = tf32r(v3);
                }
            }
        __syncthreads();

        if (tid < 64) {
            float m = Qs[tid][0];
#pragma unroll
            for (int s = 1; s < 32; s++) m = fmaxf(m, Qs[tid][s]);
            float e[32], sum = 0.f;
#pragma unroll
            for (int s = 0; s < 32; s++) { e[s] = expf(Qs[tid][s] - m); sum += e[s]; }
            float inv = 1.f / sum;
#pragma unroll
            for (int s = 0; s < 32; s++) Qs[tid][s] = e[s] * inv;
        }

        if (tid >= 64 && tid < 96) {
            const int s = tid - 64;
            float acc0 = 0.f;
#pragma unroll
            for (int r = 0; r < 64; r++) acc0 += Es[s][r];
            s0acc += acc0;
        }
        __syncthreads();

        // coalesced fp16 store of softmaxed Q (GEMM2 A operand)
        for (int idx = tid; idx < 64 * 8; idx += 128) {
            int r = idx >> 3, c4 = (idx & 7) * 4;
            float4 v = *reinterpret_cast<const float4*>(&Qs[r][c4]);
            __half2 h0 = __floats2half2_rn(v.x, v.y);
            __half2 h1 = __floats2half2_rn(v.z, v.w);
            uint2 o;
            o.x = *reinterpret_cast<unsigned*>(&h0);
            o.y = *reinterpret_cast<unsigned*>(&h1);
            *reinterpret_cast<uint2*>(
                &g_qh[(size_t)(b * SEQ + n0 + r) * QDIM + h * SL + c4]) = o;
        }

#pragma unroll
        for (int ks = 0; ks < 8; ks++) {
            unsigned af2[2][4];
#pragma unroll
            for (int mt = 0; mt < 2; mt++) {
                const int r0 = mt * 16 + g;
                af2[mt][0] = __float_as_uint(Es[r0    ][8 * ks + t    ]);
                af2[mt][1] = __float_as_uint(Es[r0 + 8][8 * ks + t    ]);
                af2[mt][2] = __float_as_uint(Es[r0    ][8 * ks + t + 4]);
                af2[mt][3] = __float_as_uint(Es[r0 + 8][8 * ks + t + 4]);
            }
#pragma unroll
            for (int nt = 0; nt < 2; nt++) {
                const int c0 = 16 * w + nt * 8 + g;
                unsigned bf2[2];
                bf2[0] = __float_as_uint(Vs[8 * ks + t    ][c0]);
                bf2[1] = __float_as_uint(Vs[8 * ks + t + 4][c0]);
#pragma unroll
                for (int mt = 0; mt < 2; mt++)
                    mma_tf32(accS1[mt][nt], af2[mt], bf2);
            }
        }
    }

    float* base = g_S1p + ((size_t)split * 64 + bh) * (SL * DH);
#pragma unroll
    for (int mt = 0; mt < 2; mt++)
#pragma unroll
        for (int nt = 0; nt < 2; nt++) {
            const int s0 = mt * 16 + g;
            const int c  = 16 * w + nt * 8 + 2 * t;
            base[(s0    ) * DH + c]     = accS1[mt][nt][0];
            base[(s0    ) * DH + c + 1] = accS1[mt][nt][1];
            base[(s0 + 8) * DH + c]     = accS1[mt][nt][2];
            base[(s0 + 8) * DH + c + 1] = accS1[mt][nt][3];
        }
    if (tid >= 64 && tid < 96)
        g_S0p[((size_t)split * 64 + bh) * SL + (tid - 64)] = s0acc;
}

// ---------------- kv finalize (round-6) ----------------
__global__ __launch_bounds__(256) void kv_final_kernel()
{
    int idx = blockIdx.x * 256 + threadIdx.x;
    if (idx >= 64 * SL * DH) return;
    int bh = idx >> 11;
    int sc = idx & 2047;
    int s  = sc >> 6;
    float s1 = 0.f, s0 = 0.f;
    for (int sp = 0; sp < KV_SPLITS; sp++) {
        s1 += g_S1p[((size_t)sp * 64 + bh) * (SL * DH) + sc];
        s0 += g_S0p[((size_t)sp * 64 + bh) * SL + s];
    }
    g_kv[idx] = s1 / s0;
}

// ---------------- Z prep: writes Z in k-paired fp16 layout for GEMM2 B operand ----------------
__global__ __launch_bounds__(256) void zprep_kernel(const float* __restrict__ W_out)
{
    const int cb = blockIdx.x;
    const int h  = blockIdx.y;
    const int b  = blockIdx.z;
    const int bh = b * HEADS + h;
    const int tid = threadIdx.x;

    __shared__ float kvs[32][64];
    __shared__ float Wos[64][64];

    for (int idx = tid; idx < SL * DH; idx += 256)
        kvs[idx >> 6][idx & 63] = g_kv[(size_t)bh * (SL * DH) + idx];
    for (int idx = tid; idx < 64 * 64; idx += 256) {
        int r = idx >> 6, c = idx & 63;
        Wos[r][c] = W_out[(size_t)(h * DH + r) * DIM + cb * 64 + c];
    }
    __syncthreads();

    for (int idx = tid; idx < SL * 64; idx += 256) {
        int s = idx >> 6, c = idx & 63;
        float d = 0.f;
#pragma unroll
        for (int k = 0; k < 64; k++) d = fmaf(kvs[s][k], Wos[k][c], d);
        const int kidx = h * SL + s;            // global k index 0..255
        const int n    = cb * 64 + c;           // output col
        g_Zp[(size_t)b * QDIM * DIM + ((size_t)(kidx >> 1) * DIM + n) * 2 + (kidx & 1)]
            = __float2half(d);
    }
}

// ---------------- launch ----------------
extern "C" void kernel_launch(void* const* d_in, const int* in_sizes, int n_in,
                              void* d_out, int out_size)
{
    const float* x     = (const float*)d_in[0];
    const float* W_in  = (const float*)d_in[1];
    const float* b_in  = (const float*)d_in[2];
    const float* Wq    = (const float*)d_in[3];
    const float* Wk    = (const float*)d_in[4];
    const float* Wv    = (const float*)d_in[5];
    const float* W_out = (const float*)d_in[6];
    const float* b_out = (const float*)d_in[7];
    float* out = (float*)d_out;

    float  *xmid;
    __half *xh, *qh, *Wp, *Zp;
    cudaGetSymbolAddress((void**)&xmid, g_xmid);
    cudaGetSymbolAddress((void**)&xh, g_xh);
    cudaGetSymbolAddress((void**)&qh, g_qh);
    cudaGetSymbolAddress((void**)&Wp, g_Wp);
    cudaGetSymbolAddress((void**)&Zp, g_Zp);

    // 0a) x -> fp16
    const int n4 = MTOT * DIM / 4;
    f2h_kernel<<<(n4 + 255) / 256, 256>>>(
        (const float4*)x, (uint2*)xh, n4);
    // 0b) W_in -> k-paired fp16
    wpair_kernel<<<(DIM * DIM + 255) / 256, 256>>>(W_in, Wp, DIM, DIM);

    // 1) x_mid = x @ W_in + b_in   (fp16 mma, K=512, fp32 out)
    dim3 g1(DIM / 128, MTOT / 128, 1);
    h16gemm_bias_kernel<<<g1, 256>>>(xh, (const __half2*)Wp, b_in, xmid, DIM, 0, 0, 0);

    // 2) fused: q-softmax -> g_qh (fp16), kv split partials
    dim3 kvGrid(KV_SPLITS, HEADS, BATCH);
    kvq_fused_kernel<<<kvGrid, 128>>>(xmid, Wq, Wk, Wv);

    // 3) kv finalize
    kv_final_kernel<<<(64 * SL * DH + 255) / 256, 256>>>();

    // 4) Z = kv @ W_out -> k-paired fp16
    dim3 zGrid(DIM / 64, HEADS, BATCH);
    zprep_kernel<<<zGrid, 256>>>(W_out);

    // 5) out = Q @ Z_b + b_out   (fp16 mma, K=256, batched over z)
    dim3 g2(DIM / 128, SEQ / 128, BATCH);
    h16gemm_bias_kernel<<<g2, 256>>>(qh, (const __half2*)Zp, b_out, out, QDIM,
                                     (size_t)SEQ * QDIM,
                                     (size_t)QDIM * DIM / 2,
                                     (size_t)SEQ * DIM);
}

// round 12
// speedup vs baseline: 1.4216x; 1.1472x over previous
#include <cuda_runtime.h>
#include <cuda_fp16.h>
#include <math.h>

#define BATCH 8
#define SEQ   8192
#define DIM   512
#define HEADS 8
#define DH    64
#define SL    32
#define MTOT  (BATCH * SEQ)
#define KV_SPLITS 64
#define QDIM  (HEADS * SL)        // 256

// ---------------- device scratch ----------------
__device__ __half g_xmid[(size_t)MTOT * DIM];          // fp16 x_mid (only kvq consumes it)
__device__ __half g_xh  [(size_t)MTOT * DIM];          // fp16 copy of x
__device__ __half g_qh  [(size_t)MTOT * QDIM];         // softmaxed Q, fp16
__device__ float  g_S1p [(size_t)KV_SPLITS * 64 * SL * DH];
__device__ float  g_S0p [(size_t)KV_SPLITS * 64 * SL];
__device__ float  g_kv  [(size_t)64 * SL * DH];
__device__ __half g_Wp  [(size_t)DIM * DIM];           // W_in in k-paired fp16 layout
__device__ __half g_Zp  [(size_t)BATCH * QDIM * DIM];  // Z per batch, k-paired fp16 layout

__device__ __forceinline__ unsigned f2tf32(float f) {
    unsigned u;
    asm("cvt.rna.tf32.f32 %0, %1;" : "=r"(u) : "f"(f));
    return u;
}
__device__ __forceinline__ float tf32r(float f) { return __uint_as_float(f2tf32(f)); }
__device__ __forceinline__ void mma_tf32(float* c, const unsigned* a, const unsigned* b) {
    asm volatile(
        "mma.sync.aligned.m16n8k8.row.col.f32.tf32.tf32.f32 "
        "{%0,%1,%2,%3}, {%4,%5,%6,%7}, {%8,%9}, {%0,%1,%2,%3};"
        : "+f"(c[0]), "+f"(c[1]), "+f"(c[2]), "+f"(c[3])
        : "r"(a[0]), "r"(a[1]), "r"(a[2]), "r"(a[3]), "r"(b[0]), "r"(b[1]));
}
__device__ __forceinline__ void mma_f16(float* c, const unsigned* a, const unsigned* b) {
    asm volatile(
        "mma.sync.aligned.m16n8k16.row.col.f32.f16.f16.f32 "
        "{%0,%1,%2,%3}, {%4,%5,%6,%7}, {%8,%9}, {%0,%1,%2,%3};"
        : "+f"(c[0]), "+f"(c[1]), "+f"(c[2]), "+f"(c[3])
        : "r"(a[0]), "r"(a[1]), "r"(a[2]), "r"(a[3]), "r"(b[0]), "r"(b[1]));
}
__device__ __forceinline__ unsigned smem_u32(const void* p) {
    return (unsigned)__cvta_generic_to_shared(p);
}
#define CP16(dst, src) asm volatile("cp.async.cg.shared.global [%0], [%1], 16;" :: "r"(dst), "l"(src))
#define CP_COMMIT()    asm volatile("cp.async.commit_group;")
#define CP_WAIT1()     asm volatile("cp.async.wait_group 1;")
#define CP_WAIT0()     asm volatile("cp.async.wait_group 0;")

// ---------------- fp32 -> fp16 bulk convert ----------------
__global__ __launch_bounds__(256) void f2h_kernel(
    const float4* __restrict__ in, uint2* __restrict__ out, int n4)
{
    int i = blockIdx.x * 256 + threadIdx.x;
    if (i >= n4) return;
    float4 v = in[i];
    __half2 h0 = __floats2half2_rn(v.x, v.y);
    __half2 h1 = __floats2half2_rn(v.z, v.w);
    uint2 o;
    o.x = *reinterpret_cast<unsigned*>(&h0);
    o.y = *reinterpret_cast<unsigned*>(&h1);
    out[i] = o;
}

// ---------------- W -> k-paired fp16 layout ----------------
__global__ __launch_bounds__(256) void wpair_kernel(
    const float* __restrict__ W, __half* __restrict__ Wp, int K, int N)
{
    int idx = blockIdx.x * 256 + threadIdx.x;
    if (idx >= K * N) return;
    int k = idx / N, n = idx - k * N;
    Wp[((size_t)(k >> 1) * N + n) * 2 + (k & 1)] = __float2half(W[idx]);
}

// ---------------- FP16 GEMM: C[M,512] = A[M,K](h) @ B(paired h) + bias; fp32 or fp16 out ------
template<bool HALF_OUT>
__global__ __launch_bounds__(256) void h16gemm_bias_kernel(
    const __half* __restrict__ A, const __half2* __restrict__ Bp,
    const float* __restrict__ bias, void* __restrict__ Cv, int K,
    size_t zStrideA, size_t zStrideB, size_t zStrideC)
{
    const int N = 512;
    __shared__ __half  As[2][128][24];
    __shared__ __half2 Bs[2][8][136];

    const int tid  = threadIdx.x;
    const int warp = tid >> 5;
    const int lane = tid & 31;
    const int g = lane >> 2;
    const int t = lane & 3;

    const int rowBase = blockIdx.y * 128;
    const int colBase = blockIdx.x * 128;
    const int wm = (warp & 3) * 32;
    const int wn = (warp >> 2) * 64;

    A  += zStrideA * blockIdx.z;
    Bp += zStrideB * blockIdx.z;
    const size_t cBase = zStrideC * blockIdx.z;

    float acc[2][8][4];
#pragma unroll
    for (int mt = 0; mt < 2; mt++)
#pragma unroll
        for (int nt = 0; nt < 8; nt++)
#pragma unroll
            for (int i = 0; i < 4; i++) acc[mt][nt][i] = 0.f;

    const int aRow = tid >> 1;
    const int aOff = (tid & 1) * 8;
    const int bKK  = tid >> 5;
    const int bN4  = (tid & 31) * 4;

    const __half*  Ag = A + (size_t)(rowBase + aRow) * K + aOff;
    const __half2* Bg = Bp + (size_t)bKK * N + colBase + bN4;

    unsigned sA = smem_u32(&As[0][aRow][aOff]);
    unsigned sB = smem_u32(&Bs[0][bKK][bN4]);
    const unsigned strideA = 128 * 24 * 2;
    const unsigned strideB = 8 * 136 * 4;

    CP16(sA, Ag);
    CP16(sB, Bg);
    CP_COMMIT();

    const int nIter = K >> 4;
#pragma unroll 1
    for (int it = 0; it < nIter; it++) {
        const int kt = it * 16;
        const int cur = it & 1;
        if (it + 1 < nIter) {
            const unsigned offA = (cur ^ 1) ? strideA : 0;
            const unsigned offB = (cur ^ 1) ? strideB : 0;
            CP16(sA + offA, Ag + kt + 16);
            CP16(sB + offB, Bg + (size_t)(it + 1) * 8 * N);
            CP_COMMIT();
            CP_WAIT1();
        } else {
            CP_WAIT0();
        }
        __syncthreads();

        unsigned af[2][4], bf[8][2];
#pragma unroll
        for (int mt = 0; mt < 2; mt++) {
            const int r0 = wm + mt * 16 + g;
            af[mt][0] = *reinterpret_cast<const unsigned*>(&As[cur][r0    ][2 * t    ]);
            af[mt][1] = *reinterpret_cast<const unsigned*>(&As[cur][r0 + 8][2 * t    ]);
            af[mt][2] = *reinterpret_cast<const unsigned*>(&As[cur][r0    ][2 * t + 8]);
            af[mt][3] = *reinterpret_cast<const unsigned*>(&As[cur][r0 + 8][2 * t + 8]);
        }
#pragma unroll
        for (int nt = 0; nt < 8; nt++) {
            const int c0 = wn + nt * 8 + g;
            bf[nt][0] = *reinterpret_cast<const unsigned*>(&Bs[cur][t    ][c0]);
            bf[nt][1] = *reinterpret_cast<const unsigned*>(&Bs[cur][t + 4][c0]);
        }
#pragma unroll
        for (int mt = 0; mt < 2; mt++)
#pragma unroll
            for (int nt = 0; nt < 8; nt++)
                mma_f16(acc[mt][nt], af[mt], bf[nt]);
        __syncthreads();
    }

#pragma unroll
    for (int nt = 0; nt < 8; nt++) {
        const int col = colBase + wn + nt * 8 + 2 * t;
        const float bx = bias[col], by = bias[col + 1];
#pragma unroll
        for (int mt = 0; mt < 2; mt++) {
            const int row0 = rowBase + wm + mt * 16 + g;
            float2 o0, o1;
            o0.x = acc[mt][nt][0] + bx; o0.y = acc[mt][nt][1] + by;
            o1.x = acc[mt][nt][2] + bx; o1.y = acc[mt][nt][3] + by;
            if (HALF_OUT) {
                __half* C = reinterpret_cast<__half*>(Cv) + cBase;
                __half2 h0 = __floats2half2_rn(o0.x, o0.y);
                __half2 h1 = __floats2half2_rn(o1.x, o1.y);
                *reinterpret_cast<__half2*>(&C[(size_t)row0 * N + col])       = h0;
                *reinterpret_cast<__half2*>(&C[(size_t)(row0 + 8) * N + col]) = h1;
            } else {
                float* C = reinterpret_cast<float*>(Cv) + cBase;
                *reinterpret_cast<float2*>(&C[(size_t)row0 * N + col])       = o0;
                *reinterpret_cast<float2*>(&C[(size_t)(row0 + 8) * N + col]) = o1;
            }
        }
    }
}

// ---------------- Fused kv + q kernel: fp16 projection mma, fp16 X input ----------------
// grid (KV_SPLITS, HEADS, BATCH), 128 threads (4 warps), 128 tokens per block (2 chunks of 64).
// P = X(64x64,h) @ [Wq|Wk|Wv](64x128,h) via m16n8k16; epilogue/softmax/S1-mma as round 6.
__global__ __launch_bounds__(128) void kvq_fused_kernel(
    const __half* __restrict__ xmid, const float* __restrict__ Wq,
    const float* __restrict__ Wk, const float* __restrict__ Wv)
{
    __shared__ __half2 Wsp[32][136];   // 32 k-pairs x 128 cols (+8 pad); (8t+g)%32 conflict-free
    __shared__ __half  Xs[64][72];     // word pattern (4g+t)%32 conflict-free
    __shared__ float   Es[32][68];
    __shared__ float   Vs[64][72];
    __shared__ float   Qs[64][36];

    const int split = blockIdx.x;
    const int h = blockIdx.y;
    const int b = blockIdx.z;
    const int bh = b * HEADS + h;
    const int tid = threadIdx.x;
    const int w = tid >> 5;
    const int lane = tid & 31;
    const int g = lane >> 2;
    const int t = lane & 3;

    // weights -> k-paired fp16 smem
    __half* WspH = reinterpret_cast<__half*>(Wsp);
    for (int idx = tid; idx < 64 * 32; idx += 128) {
        int k = idx >> 5, s = idx & 31;
        WspH[((k >> 1) * 136 + s) * 2 + (k & 1)] = __float2half(Wq[idx]);
    }
    for (int idx = tid; idx < 64 * 32; idx += 128) {
        int k = idx >> 5, s = idx & 31;
        WspH[((k >> 1) * 136 + 32 + s) * 2 + (k & 1)] = __float2half(Wk[idx]);
    }
    for (int idx = tid; idx < 64 * 64; idx += 128) {
        int k = idx >> 6, c = idx & 63;
        WspH[((k >> 1) * 136 + 64 + c) * 2 + (k & 1)] = __float2half(Wv[idx]);
    }
    __syncthreads();

    // cache weight B-fragments: warp w owns cols [32w, 32w+32): 4 nt x 4 ks x 2 = 32 regs
    unsigned bfw[4][4][2];
    const unsigned* WspW = reinterpret_cast<const unsigned*>(Wsp);
#pragma unroll
    for (int nt = 0; nt < 4; nt++)
#pragma unroll
        for (int ks = 0; ks < 4; ks++) {
            const int c0 = 32 * w + nt * 8 + g;
            bfw[nt][ks][0] = WspW[(8 * ks + t    ) * 136 + c0];
            bfw[nt][ks][1] = WspW[(8 * ks + t + 4) * 136 + c0];
        }

    float accS1[2][2][4];
#pragma unroll
    for (int mt = 0; mt < 2; mt++)
#pragma unroll
        for (int nt = 0; nt < 2; nt++)
#pragma unroll
            for (int i = 0; i < 4; i++) accS1[mt][nt][i] = 0.f;
    float s0acc = 0.f;

#pragma unroll 1
    for (int chunk = 0; chunk < 2; chunk++) {
        const int n0 = split * 128 + chunk * 64;
        __syncthreads();

        // X tile: 64 rows x 64 halves, vectorized uint4 (8 halves)
        for (int idx = tid; idx < 64 * 8; idx += 128) {
            int r = idx >> 3, c8 = (idx & 7) * 8;
            uint4 v = *reinterpret_cast<const uint4*>(
                &xmid[(size_t)(b * SEQ + n0 + r) * DIM + h * DH + c8]);
            *reinterpret_cast<uint4*>(&Xs[r][c8]) = v;
        }
        __syncthreads();

        // projection mma: 64 rows (4 mt) x warp's 32 cols (4 nt), k=64 -> 4 fp16 k-steps
        float pacc[4][4][4];
#pragma unroll
        for (int mt = 0; mt < 4; mt++)
#pragma unroll
            for (int nt = 0; nt < 4; nt++)
#pragma unroll
                for (int i = 0; i < 4; i++) pacc[mt][nt][i] = 0.f;

#pragma unroll
        for (int ks = 0; ks < 4; ks++) {
            unsigned af[4][4];
#pragma unroll
            for (int mt = 0; mt < 4; mt++) {
                const int r0 = mt * 16 + g;
                af[mt][0] = *reinterpret_cast<const unsigned*>(&Xs[r0    ][16 * ks + 2 * t    ]);
                af[mt][1] = *reinterpret_cast<const unsigned*>(&Xs[r0 + 8][16 * ks + 2 * t    ]);
                af[mt][2] = *reinterpret_cast<const unsigned*>(&Xs[r0    ][16 * ks + 2 * t + 8]);
                af[mt][3] = *reinterpret_cast<const unsigned*>(&Xs[r0 + 8][16 * ks + 2 * t + 8]);
            }
#pragma unroll
            for (int mt = 0; mt < 4; mt++)
#pragma unroll
                for (int nt = 0; nt < 4; nt++)
                    mma_f16(pacc[mt][nt], af[mt], bfw[nt][ks]);
        }

        // epilogue by warp role (identical accumulator layout to m16n8k8)
#pragma unroll
        for (int mt = 0; mt < 4; mt++)
#pragma unroll
            for (int nt = 0; nt < 4; nt++) {
                const int c0 = 32 * w + nt * 8 + 2 * t;
                const int r0 = mt * 16 + g;
                float v0 = pacc[mt][nt][0], v1 = pacc[mt][nt][1];
                float v2 = pacc[mt][nt][2], v3 = pacc[mt][nt][3];
                if (w == 0) {
                    Qs[r0    ][c0]     = v0;
                    Qs[r0    ][c0 + 1] = v1;
                    Qs[r0 + 8][c0]     = v2;
                    Qs[r0 + 8][c0 + 1] = v3;
                } else if (w == 1) {
                    const int s = c0 - 32;
                    Es[s    ][r0]     = tf32r(expf(v0));
                    Es[s + 1][r0]     = tf32r(expf(v1));
                    Es[s    ][r0 + 8] = tf32r(expf(v2));
                    Es[s + 1][r0 + 8] = tf32r(expf(v3));
                } else {
                    const int c = c0 - 64;
                    Vs[r0    ][c]     = tf32r(v0);
                    Vs[r0    ][c + 1] = tf32r(v1);
                    Vs[r0 + 8][c]     = tf32r(v2);
                    Vs[r0 + 8][c + 1] = tf32r(v3);
                }
            }
        __syncthreads();

        // softmax (one token per thread) + S0 column sums
        if (tid < 64) {
            float m = Qs[tid][0];
#pragma unroll
            for (int s = 1; s < 32; s++) m = fmaxf(m, Qs[tid][s]);
            float e[32], sum = 0.f;
#pragma unroll
            for (int s = 0; s < 32; s++) { e[s] = expf(Qs[tid][s] - m); sum += e[s]; }
            float inv = 1.f / sum;
#pragma unroll
            for (int s = 0; s < 32; s++) Qs[tid][s] = e[s] * inv;
        }
        if (tid >= 64 && tid < 96) {
            const int s = tid - 64;
            float acc0 = 0.f;
#pragma unroll
            for (int r = 0; r < 64; r++) acc0 += Es[s][r];
            s0acc += acc0;
        }
        __syncthreads();

        // coalesced fp16 store of softmaxed Q
        for (int idx = tid; idx < 64 * 8; idx += 128) {
            int r = idx >> 3, c4 = (idx & 7) * 4;
            float4 v = *reinterpret_cast<const float4*>(&Qs[r][c4]);
            __half2 h0 = __floats2half2_rn(v.x, v.y);
            __half2 h1 = __floats2half2_rn(v.z, v.w);
            uint2 o;
            o.x = *reinterpret_cast<unsigned*>(&h0);
            o.y = *reinterpret_cast<unsigned*>(&h1);
            *reinterpret_cast<uint2*>(
                &g_qh[(size_t)(b * SEQ + n0 + r) * QDIM + h * SL + c4]) = o;
        }

        // S1 += Es(32x64tok) @ Vs(64tok x 64) via tf32 mma (proven path)
#pragma unroll
        for (int ks = 0; ks < 8; ks++) {
            unsigned af2[2][4];
#pragma unroll
            for (int mt = 0; mt < 2; mt++) {
                const int r0 = mt * 16 + g;
                af2[mt][0] = __float_as_uint(Es[r0    ][8 * ks + t    ]);
                af2[mt][1] = __float_as_uint(Es[r0 + 8][8 * ks + t    ]);
                af2[mt][2] = __float_as_uint(Es[r0    ][8 * ks + t + 4]);
                af2[mt][3] = __float_as_uint(Es[r0 + 8][8 * ks + t + 4]);
            }
#pragma unroll
            for (int nt = 0; nt < 2; nt++) {
                const int c0 = 16 * w + nt * 8 + g;
                unsigned bf2[2];
                bf2[0] = __float_as_uint(Vs[8 * ks + t    ][c0]);
                bf2[1] = __float_as_uint(Vs[8 * ks + t + 4][c0]);
#pragma unroll
                for (int mt = 0; mt < 2; mt++)
                    mma_tf32(accS1[mt][nt], af2[mt], bf2);
            }
        }
    }

    float* base = g_S1p + ((size_t)split * 64 + bh) * (SL * DH);
#pragma unroll
    for (int mt = 0; mt < 2; mt++)
#pragma unroll
        for (int nt = 0; nt < 2; nt++) {
            const int s0 = mt * 16 + g;
            const int c  = 16 * w + nt * 8 + 2 * t;
            base[(s0    ) * DH + c]     = accS1[mt][nt][0];
            base[(s0    ) * DH + c + 1] = accS1[mt][nt][1];
            base[(s0 + 8) * DH + c]     = accS1[mt][nt][2];
            base[(s0 + 8) * DH + c + 1] = accS1[mt][nt][3];
        }
    if (tid >= 64 && tid < 96)
        g_S0p[((size_t)split * 64 + bh) * SL + (tid - 64)] = s0acc;
}

// ---------------- kv finalize ----------------
__global__ __launch_bounds__(256) void kv_final_kernel()
{
    int idx = blockIdx.x * 256 + threadIdx.x;
    if (idx >= 64 * SL * DH) return;
    int bh = idx >> 11;
    int sc = idx & 2047;
    int s  = sc >> 6;
    float s1 = 0.f, s0 = 0.f;
    for (int sp = 0; sp < KV_SPLITS; sp++) {
        s1 += g_S1p[((size_t)sp * 64 + bh) * (SL * DH) + sc];
        s0 += g_S0p[((size_t)sp * 64 + bh) * SL + s];
    }
    g_kv[idx] = s1 / s0;
}

// ---------------- Z prep: writes Z in k-paired fp16 layout ----------------
__global__ __launch_bounds__(256) void zprep_kernel(const float* __restrict__ W_out)
{
    const int cb = blockIdx.x;
    const int h  = blockIdx.y;
    const int b  = blockIdx.z;
    const int bh = b * HEADS + h;
    const int tid = threadIdx.x;

    __shared__ float kvs[32][64];
    __shared__ float Wos[64][64];

    for (int idx = tid; idx < SL * DH; idx += 256)
        kvs[idx >> 6][idx & 63] = g_kv[(size_t)bh * (SL * DH) + idx];
    for (int idx = tid; idx < 64 * 64; idx += 256) {
        int r = idx >> 6, c = idx & 63;
        Wos[r][c] = W_out[(size_t)(h * DH + r) * DIM + cb * 64 + c];
    }
    __syncthreads();

    for (int idx = tid; idx < SL * 64; idx += 256) {
        int s = idx >> 6, c = idx & 63;
        float d = 0.f;
#pragma unroll
        for (int k = 0; k < 64; k++) d = fmaf(kvs[s][k], Wos[k][c], d);
        const int kidx = h * SL + s;
        const int n    = cb * 64 + c;
        g_Zp[(size_t)b * QDIM * DIM + ((size_t)(kidx >> 1) * DIM + n) * 2 + (kidx & 1)]
            = __float2half(d);
    }
}

// ---------------- launch ----------------
extern "C" void kernel_launch(void* const* d_in, const int* in_sizes, int n_in,
                              void* d_out, int out_size)
{
    const float* x     = (const float*)d_in[0];
    const float* W_in  = (const float*)d_in[1];
    const float* b_in  = (const float*)d_in[2];
    const float* Wq    = (const float*)d_in[3];
    const float* Wk    = (const float*)d_in[4];
    const float* Wv    = (const float*)d_in[5];
    const float* W_out = (const float*)d_in[6];
    const float* b_out = (const float*)d_in[7];
    float* out = (float*)d_out;

    __half *xmid, *xh, *qh, *Wp, *Zp;
    cudaGetSymbolAddress((void**)&xmid, g_xmid);
    cudaGetSymbolAddress((void**)&xh, g_xh);
    cudaGetSymbolAddress((void**)&qh, g_qh);
    cudaGetSymbolAddress((void**)&Wp, g_Wp);
    cudaGetSymbolAddress((void**)&Zp, g_Zp);

    // 0a) x -> fp16
    const int n4 = MTOT * DIM / 4;
    f2h_kernel<<<(n4 + 255) / 256, 256>>>((const float4*)x, (uint2*)xh, n4);
    // 0b) W_in -> k-paired fp16
    wpair_kernel<<<(DIM * DIM + 255) / 256, 256>>>(W_in, Wp, DIM, DIM);

    // 1) x_mid = x @ W_in + b_in   (fp16 mma, fp16 output)
    dim3 g1(DIM / 128, MTOT / 128, 1);
    h16gemm_bias_kernel<true><<<g1, 256>>>(xh, (const __half2*)Wp, b_in, xmid, DIM, 0, 0, 0);

    // 2) fused: q-softmax -> g_qh, kv split partials (fp16 projection)
    dim3 kvGrid(KV_SPLITS, HEADS, BATCH);
    kvq_fused_kernel<<<kvGrid, 128>>>(xmid, Wq, Wk, Wv);

    // 3) kv finalize
    kv_final_kernel<<<(64 * SL * DH + 255) / 256, 256>>>();

    // 4) Z = kv @ W_out -> k-paired fp16
    dim3 zGrid(DIM / 64, HEADS, BATCH);
    zprep_kernel<<<zGrid, 256>>>(W_out);

    // 5) out = Q @ Z_b + b_out   (fp16 mma, K=256, batched; fp32 output)
    dim3 g2(DIM / 128, SEQ / 128, BATCH);
    h16gemm_bias_kernel<false><<<g2, 256>>>(qh, (const __half2*)Zp, b_out, out, QDIM,
                                            (size_t)SEQ * QDIM,
                                            (size_t)QDIM * DIM / 2,
                                            (size_t)SEQ * DIM);
}

// round 13
// speedup vs baseline: 1.9226x; 1.3524x over previous
#include <cuda_runtime.h>
#include <cuda_fp16.h>
#include <math.h>

#define BATCH 8
#define SEQ   8192
#define DIM   512
#define HEADS 8
#define DH    64
#define SL    32
#define MTOT  (BATCH * SEQ)
#define KV_SPLITS 64
#define QDIM  (HEADS * SL)        // 256

// ---------------- device scratch ----------------
__device__ __half  g_xmid[(size_t)MTOT * DIM];
__device__ __half  g_xh  [(size_t)MTOT * DIM];
__device__ __half  g_qh  [(size_t)MTOT * QDIM];
__device__ float   g_S1p [(size_t)KV_SPLITS * 64 * SL * DH];
__device__ float   g_S0p [(size_t)KV_SPLITS * 64 * SL];
__device__ float   g_kv  [(size_t)64 * SL * DH];
__device__ __half  g_Wp  [(size_t)DIM * DIM];           // W_in, k-paired fp16
__device__ __half  g_Zp  [(size_t)BATCH * QDIM * DIM];  // Z, k-paired fp16
__device__ __half2 g_WC  [(size_t)32 * 128];            // [Wq|Wk|Wv] k-paired fp16: [kk][col]

__device__ __forceinline__ void mma_f16(float* c, const unsigned* a, const unsigned* b) {
    asm volatile(
        "mma.sync.aligned.m16n8k16.row.col.f32.f16.f16.f32 "
        "{%0,%1,%2,%3}, {%4,%5,%6,%7}, {%8,%9}, {%0,%1,%2,%3};"
        : "+f"(c[0]), "+f"(c[1]), "+f"(c[2]), "+f"(c[3])
        : "r"(a[0]), "r"(a[1]), "r"(a[2]), "r"(a[3]), "r"(b[0]), "r"(b[1]));
}
__device__ __forceinline__ unsigned smem_u32(const void* p) {
    return (unsigned)__cvta_generic_to_shared(p);
}
#define CP16(dst, src) asm volatile("cp.async.cg.shared.global [%0], [%1], 16;" :: "r"(dst), "l"(src))
#define CP_COMMIT()    asm volatile("cp.async.commit_group;")
#define CP_WAIT1()     asm volatile("cp.async.wait_group 1;")
#define CP_WAIT0()     asm volatile("cp.async.wait_group 0;")

// ---------------- fp32 -> fp16 bulk convert ----------------
__global__ __launch_bounds__(256) void f2h_kernel(
    const float4* __restrict__ in, uint2* __restrict__ out, int n4)
{
    int i = blockIdx.x * 256 + threadIdx.x;
    if (i >= n4) return;
    float4 v = in[i];
    __half2 h0 = __floats2half2_rn(v.x, v.y);
    __half2 h1 = __floats2half2_rn(v.z, v.w);
    uint2 o;
    o.x = *reinterpret_cast<unsigned*>(&h0);
    o.y = *reinterpret_cast<unsigned*>(&h1);
    out[i] = o;
}

// ---------------- W -> k-paired fp16 layout ----------------
__global__ __launch_bounds__(256) void wpair_kernel(
    const float* __restrict__ W, __half* __restrict__ Wp, int K, int N)
{
    int idx = blockIdx.x * 256 + threadIdx.x;
    if (idx >= K * N) return;
    int k = idx / N, n = idx - k * N;
    Wp[((size_t)(k >> 1) * N + n) * 2 + (k & 1)] = __float2half(W[idx]);
}

// ---------------- [Wq|Wk|Wv] -> combined k-paired fp16: WC[kk*128 + c] = {w(2kk,c), w(2kk+1,c)} --
__global__ __launch_bounds__(256) void wqkv_pair_kernel(
    const float* __restrict__ Wq, const float* __restrict__ Wk,
    const float* __restrict__ Wv, __half2* __restrict__ WC)
{
    int idx = blockIdx.x * 256 + threadIdx.x;   // 32*128
    if (idx >= 32 * 128) return;
    int kk = idx >> 7, c = idx & 127;
    float lo, hi;
    if (c < 32)      { lo = Wq[(2 * kk) * SL + c];        hi = Wq[(2 * kk + 1) * SL + c]; }
    else if (c < 64) { lo = Wk[(2 * kk) * SL + (c - 32)]; hi = Wk[(2 * kk + 1) * SL + (c - 32)]; }
    else             { lo = Wv[(2 * kk) * DH + (c - 64)]; hi = Wv[(2 * kk + 1) * DH + (c - 64)]; }
    WC[idx] = __floats2half2_rn(lo, hi);
}

// ---------------- FP16 GEMM (round-12 proven) ----------------
template<bool HALF_OUT>
__global__ __launch_bounds__(256) void h16gemm_bias_kernel(
    const __half* __restrict__ A, const __half2* __restrict__ Bp,
    const float* __restrict__ bias, void* __restrict__ Cv, int K,
    size_t zStrideA, size_t zStrideB, size_t zStrideC)
{
    const int N = 512;
    __shared__ __half  As[2][128][24];
    __shared__ __half2 Bs[2][8][136];

    const int tid  = threadIdx.x;
    const int warp = tid >> 5;
    const int lane = tid & 31;
    const int g = lane >> 2;
    const int t = lane & 3;

    const int rowBase = blockIdx.y * 128;
    const int colBase = blockIdx.x * 128;
    const int wm = (warp & 3) * 32;
    const int wn = (warp >> 2) * 64;

    A  += zStrideA * blockIdx.z;
    Bp += zStrideB * blockIdx.z;
    const size_t cBase = zStrideC * blockIdx.z;

    float acc[2][8][4];
#pragma unroll
    for (int mt = 0; mt < 2; mt++)
#pragma unroll
        for (int nt = 0; nt < 8; nt++)
#pragma unroll
            for (int i = 0; i < 4; i++) acc[mt][nt][i] = 0.f;

    const int aRow = tid >> 1;
    const int aOff = (tid & 1) * 8;
    const int bKK  = tid >> 5;
    const int bN4  = (tid & 31) * 4;

    const __half*  Ag = A + (size_t)(rowBase + aRow) * K + aOff;
    const __half2* Bg = Bp + (size_t)bKK * N + colBase + bN4;

    unsigned sA = smem_u32(&As[0][aRow][aOff]);
    unsigned sB = smem_u32(&Bs[0][bKK][bN4]);
    const unsigned strideA = 128 * 24 * 2;
    const unsigned strideB = 8 * 136 * 4;

    CP16(sA, Ag);
    CP16(sB, Bg);
    CP_COMMIT();

    const int nIter = K >> 4;
#pragma unroll 1
    for (int it = 0; it < nIter; it++) {
        const int kt = it * 16;
        const int cur = it & 1;
        if (it + 1 < nIter) {
            const unsigned offA = (cur ^ 1) ? strideA : 0;
            const unsigned offB = (cur ^ 1) ? strideB : 0;
            CP16(sA + offA, Ag + kt + 16);
            CP16(sB + offB, Bg + (size_t)(it + 1) * 8 * N);
            CP_COMMIT();
            CP_WAIT1();
        } else {
            CP_WAIT0();
        }
        __syncthreads();

        unsigned af[2][4], bf[8][2];
#pragma unroll
        for (int mt = 0; mt < 2; mt++) {
            const int r0 = wm + mt * 16 + g;
            af[mt][0] = *reinterpret_cast<const unsigned*>(&As[cur][r0    ][2 * t    ]);
            af[mt][1] = *reinterpret_cast<const unsigned*>(&As[cur][r0 + 8][2 * t    ]);
            af[mt][2] = *reinterpret_cast<const unsigned*>(&As[cur][r0    ][2 * t + 8]);
            af[mt][3] = *reinterpret_cast<const unsigned*>(&As[cur][r0 + 8][2 * t + 8]);
        }
#pragma unroll
        for (int nt = 0; nt < 8; nt++) {
            const int c0 = wn + nt * 8 + g;
            bf[nt][0] = *reinterpret_cast<const unsigned*>(&Bs[cur][t    ][c0]);
            bf[nt][1] = *reinterpret_cast<const unsigned*>(&Bs[cur][t + 4][c0]);
        }
#pragma unroll
        for (int mt = 0; mt < 2; mt++)
#pragma unroll
            for (int nt = 0; nt < 8; nt++)
                mma_f16(acc[mt][nt], af[mt], bf[nt]);
        __syncthreads();
    }

#pragma unroll
    for (int nt = 0; nt < 8; nt++) {
        const int col = colBase + wn + nt * 8 + 2 * t;
        const float bx = bias[col], by = bias[col + 1];
#pragma unroll
        for (int mt = 0; mt < 2; mt++) {
            const int row0 = rowBase + wm + mt * 16 + g;
            float2 o0, o1;
            o0.x = acc[mt][nt][0] + bx; o0.y = acc[mt][nt][1] + by;
            o1.x = acc[mt][nt][2] + bx; o1.y = acc[mt][nt][3] + by;
            if (HALF_OUT) {
                __half* C = reinterpret_cast<__half*>(Cv) + cBase;
                __half2 h0 = __floats2half2_rn(o0.x, o0.y);
                __half2 h1 = __floats2half2_rn(o1.x, o1.y);
                *reinterpret_cast<__half2*>(&C[(size_t)row0 * N + col])       = h0;
                *reinterpret_cast<__half2*>(&C[(size_t)(row0 + 8) * N + col]) = h1;
            } else {
                float* C = reinterpret_cast<float*>(Cv) + cBase;
                *reinterpret_cast<float2*>(&C[(size_t)row0 * N + col])       = o0;
                *reinterpret_cast<float2*>(&C[(size_t)(row0 + 8) * N + col]) = o1;
            }
        }
    }
}

// ---------------- Fused kv + q kernel: fully fp16 mma, cp.async loads, smem alias --------------
// grid (KV_SPLITS, HEADS, BATCH), 128 threads (4 warps), 128 tokens per block (2 chunks of 64).
__global__ __launch_bounds__(128) void kvq_fused_kernel(
    const __half* __restrict__ xmid, const __half2* __restrict__ WC)
{
    // alias region: Wsp[32][136] half2 (17408B)  -->  Es[32][72] half (4608B) + Vsp[32][72] half2 (9216B)
    __shared__ __align__(16) char smA[17408];
    __shared__ __align__(16) __half Xs[64][72];
    __shared__ float Qs[64][36];

    __half2 (*Wsp)[136] = reinterpret_cast<__half2(*)[136]>(smA);
    __half*  Es  = reinterpret_cast<__half*>(smA);                // [32][72] halves
    __half*  VspH = reinterpret_cast<__half*>(smA + 4608);        // paired V, half view
    const unsigned* WspW = reinterpret_cast<const unsigned*>(smA);
    const unsigned* VspW = reinterpret_cast<const unsigned*>(smA + 4608);

    const int split = blockIdx.x;
    const int h = blockIdx.y;
    const int b = blockIdx.z;
    const int bh = b * HEADS + h;
    const int tid = threadIdx.x;
    const int w = tid >> 5;
    const int lane = tid & 31;
    const int g = lane >> 2;
    const int t = lane & 3;

    const unsigned WspBase = smem_u32(smA);
    const unsigned XsBase  = smem_u32(Xs);

    // prologue: weights + X chunk0 via cp.async
#pragma unroll
    for (int i = 0; i < 8; i++) {
        int idx = tid + i * 128;          // 0..1023
        int row = idx >> 5, seg = idx & 31;
        CP16(WspBase + row * 544 + seg * 16, WC + row * 128 + seg * 4);
    }
    {
        const int n0 = split * 128;
#pragma unroll
        for (int i = 0; i < 4; i++) {
            int idx = tid + i * 128;      // 0..511
            int r = idx >> 3, c8 = (idx & 7) * 8;
            CP16(XsBase + r * 144 + c8 * 2,
                 xmid + (size_t)(b * SEQ + n0 + r) * DIM + h * DH + c8);
        }
    }
    CP_COMMIT();
    CP_WAIT0();
    __syncthreads();

    // cache weight B-fragments: warp w owns cols [32w, 32w+32): 4 nt x 4 ks x 2 = 32 regs
    unsigned bfw[4][4][2];
#pragma unroll
    for (int nt = 0; nt < 4; nt++)
#pragma unroll
        for (int ks = 0; ks < 4; ks++) {
            const int c0 = 32 * w + nt * 8 + g;
            bfw[nt][ks][0] = WspW[(8 * ks + t    ) * 136 + c0];
            bfw[nt][ks][1] = WspW[(8 * ks + t + 4) * 136 + c0];
        }
    __syncthreads();   // Wsp reads done -> alias region (Es/Vsp) writable

    float accS1[2][2][4];
#pragma unroll
    for (int mt = 0; mt < 2; mt++)
#pragma unroll
        for (int nt = 0; nt < 2; nt++)
#pragma unroll
            for (int i = 0; i < 4; i++) accS1[mt][nt][i] = 0.f;
    float s0acc = 0.f;

#pragma unroll 1
    for (int chunk = 0; chunk < 2; chunk++) {
        const int n0 = split * 128 + chunk * 64;

        // projection: per 16-row block (mt), mma then epilogue -> pacc stays 16 regs
#pragma unroll
        for (int mt = 0; mt < 4; mt++) {
            float pacc[4][4];
#pragma unroll
            for (int nt = 0; nt < 4; nt++)
#pragma unroll
                for (int i = 0; i < 4; i++) pacc[nt][i] = 0.f;

#pragma unroll
            for (int ks = 0; ks < 4; ks++) {
                const int r0 = mt * 16 + g;
                unsigned af[4];
                af[0] = *reinterpret_cast<const unsigned*>(&Xs[r0    ][16 * ks + 2 * t    ]);
                af[1] = *reinterpret_cast<const unsigned*>(&Xs[r0 + 8][16 * ks + 2 * t    ]);
                af[2] = *reinterpret_cast<const unsigned*>(&Xs[r0    ][16 * ks + 2 * t + 8]);
                af[3] = *reinterpret_cast<const unsigned*>(&Xs[r0 + 8][16 * ks + 2 * t + 8]);
#pragma unroll
                for (int nt = 0; nt < 4; nt++)
                    mma_f16(pacc[nt], af, bfw[nt][ks]);
            }

            // epilogue for this mt, by warp role
#pragma unroll
            for (int nt = 0; nt < 4; nt++) {
                const int c0 = 32 * w + nt * 8 + 2 * t;
                const int r0 = mt * 16 + g;
                float v0 = pacc[nt][0], v1 = pacc[nt][1];
                float v2 = pacc[nt][2], v3 = pacc[nt][3];
                if (w == 0) {                           // Q raw fp32
                    Qs[r0    ][c0]     = v0;
                    Qs[r0    ][c0 + 1] = v1;
                    Qs[r0 + 8][c0]     = v2;
                    Qs[r0 + 8][c0 + 1] = v3;
                } else if (w == 1) {                    // E = exp(K), transposed, fp16
                    const int s = c0 - 32;
                    Es[(s    ) * 72 + r0]     = __float2half(expf(v0));
                    Es[(s + 1) * 72 + r0]     = __float2half(expf(v1));
                    Es[(s    ) * 72 + r0 + 8] = __float2half(expf(v2));
                    Es[(s + 1) * 72 + r0 + 8] = __float2half(expf(v3));
                } else {                                // V, token-paired fp16 [kk][c]
                    const int c = c0 - 64;
                    VspH[(r0 >> 1) * 144 + c * 2 + (r0 & 1)]             = __float2half(v0);
                    VspH[(r0 >> 1) * 144 + (c + 1) * 2 + (r0 & 1)]       = __float2half(v1);
                    VspH[((r0 + 8) >> 1) * 144 + c * 2 + ((r0 + 8) & 1)] = __float2half(v2);
                    VspH[((r0 + 8) >> 1) * 144 + (c + 1) * 2 + ((r0 + 8) & 1)] = __float2half(v3);
                }
            }
        }
        __syncthreads();

        // prefetch next X chunk (overlaps softmax/S1)
        if (chunk == 0) {
            const int n1 = split * 128 + 64;
#pragma unroll
            for (int i = 0; i < 4; i++) {
                int idx = tid + i * 128;
                int r = idx >> 3, c8 = (idx & 7) * 8;
                CP16(XsBase + r * 144 + c8 * 2,
                     xmid + (size_t)(b * SEQ + n1 + r) * DIM + h * DH + c8);
            }
            CP_COMMIT();
        }

        // softmax (one token per thread) + S0 column sums
        if (tid < 64) {
            float m = Qs[tid][0];
#pragma unroll
            for (int s = 1; s < 32; s++) m = fmaxf(m, Qs[tid][s]);
            float e[32], sum = 0.f;
#pragma unroll
            for (int s = 0; s < 32; s++) { e[s] = expf(Qs[tid][s] - m); sum += e[s]; }
            float inv = 1.f / sum;
#pragma unroll
            for (int s = 0; s < 32; s++) Qs[tid][s] = e[s] * inv;
        }
        if (tid >= 64 && tid < 96) {
            const int s = tid - 64;
            const __half2* Erow = reinterpret_cast<const __half2*>(&Es[s * 72]);
            float acc0 = 0.f;
#pragma unroll
            for (int r2 = 0; r2 < 32; r2++) {
                float2 f = __half22float2(Erow[r2]);
                acc0 += f.x + f.y;
            }
            s0acc += acc0;
        }
        __syncthreads();

        // coalesced fp16 store of softmaxed Q
        for (int idx = tid; idx < 64 * 8; idx += 128) {
            int r = idx >> 3, c4 = (idx & 7) * 4;
            float4 v = *reinterpret_cast<const float4*>(&Qs[r][c4]);
            __half2 h0 = __floats2half2_rn(v.x, v.y);
            __half2 h1 = __floats2half2_rn(v.z, v.w);
            uint2 o;
            o.x = *reinterpret_cast<unsigned*>(&h0);
            o.y = *reinterpret_cast<unsigned*>(&h1);
            *reinterpret_cast<uint2*>(
                &g_qh[(size_t)(b * SEQ + n0 + r) * QDIM + h * SL + c4]) = o;
        }

        // S1 += Es(32 x 64tok) @ V(64tok x 64) via fp16 mma; warp w: cols [16w, 16w+16)
#pragma unroll
        for (int ks = 0; ks < 4; ks++) {
            unsigned af2[2][4];
#pragma unroll
            for (int mt = 0; mt < 2; mt++) {
                const int r0 = mt * 16 + g;
                af2[mt][0] = *reinterpret_cast<const unsigned*>(&Es[(r0    ) * 72 + 16 * ks + 2 * t    ]);
                af2[mt][1] = *reinterpret_cast<const unsigned*>(&Es[(r0 + 8) * 72 + 16 * ks + 2 * t    ]);
                af2[mt][2] = *reinterpret_cast<const unsigned*>(&Es[(r0    ) * 72 + 16 * ks + 2 * t + 8]);
                af2[mt][3] = *reinterpret_cast<const unsigned*>(&Es[(r0 + 8) * 72 + 16 * ks + 2 * t + 8]);
            }
#pragma unroll
            for (int nt = 0; nt < 2; nt++) {
                const int c0 = 16 * w + nt * 8 + g;
                unsigned bf2[2];
                bf2[0] = VspW[(8 * ks + t    ) * 72 + c0];
                bf2[1] = VspW[(8 * ks + t + 4) * 72 + c0];
#pragma unroll
                for (int mt = 0; mt < 2; mt++)
                    mma_f16(accS1[mt][nt], af2[mt], bf2);
            }
        }

        if (chunk == 0) { CP_WAIT0(); }
        __syncthreads();   // Es/Vsp consumed; Xs refreshed -> next chunk safe
    }

    float* base = g_S1p + ((size_t)split * 64 + bh) * (SL * DH);
#pragma unroll
    for (int mt = 0; mt < 2; mt++)
#pragma unroll
        for (int nt = 0; nt < 2; nt++) {
            const int s0 = mt * 16 + g;
            const int c  = 16 * w + nt * 8 + 2 * t;
            base[(s0    ) * DH + c]     = accS1[mt][nt][0];
            base[(s0    ) * DH + c + 1] = accS1[mt][nt][1];
            base[(s0 + 8) * DH + c]     = accS1[mt][nt][2];
            base[(s0 + 8) * DH + c + 1] = accS1[mt][nt][3];
        }
    if (tid >= 64 && tid < 96)
        g_S0p[((size_t)split * 64 + bh) * SL + (tid - 64)] = s0acc;
}

// ---------------- kv finalize ----------------
__global__ __launch_bounds__(256) void kv_final_kernel()
{
    int idx = blockIdx.x * 256 + threadIdx.x;
    if (idx >= 64 * SL * DH) return;
    int bh = idx >> 11;
    int sc = idx & 2047;
    int s  = sc >> 6;
    float s1 = 0.f, s0 = 0.f;
    for (int sp = 0; sp < KV_SPLITS; sp++) {
        s1 += g_S1p[((size_t)sp * 64 + bh) * (SL * DH) + sc];
        s0 += g_S0p[((size_t)sp * 64 + bh) * SL + s];
    }
    g_kv[idx] = s1 / s0;
}

// ---------------- Z prep: writes Z in k-paired fp16 layout ----------------
__global__ __launch_bounds__(256) void zprep_kernel(const float* __restrict__ W_out)
{
    const int cb = blockIdx.x;
    const int h  = blockIdx.y;
    const int b  = blockIdx.z;
    const int bh = b * HEADS + h;
    const int tid = threadIdx.x;

    __shared__ float kvs[32][64];
    __shared__ float Wos[64][64];

    for (int idx = tid; idx < SL * DH; idx += 256)
        kvs[idx >> 6][idx & 63] = g_kv[(size_t)bh * (SL * DH) + idx];
    for (int idx = tid; idx < 64 * 64; idx += 256) {
        int r = idx >> 6, c = idx & 63;
        Wos[r][c] = W_out[(size_t)(h * DH + r) * DIM + cb * 64 + c];
    }
    __syncthreads();

    for (int idx = tid; idx < SL * 64; idx += 256) {
        int s = idx >> 6, c = idx & 63;
        float d = 0.f;
#pragma unroll
        for (int k = 0; k < 64; k++) d = fmaf(kvs[s][k], Wos[k][c], d);
        const int kidx = h * SL + s;
        const int n    = cb * 64 + c;
        g_Zp[(size_t)b * QDIM * DIM + ((size_t)(kidx >> 1) * DIM + n) * 2 + (kidx & 1)]
            = __float2half(d);
    }
}

// ---------------- launch ----------------
extern "C" void kernel_launch(void* const* d_in, const int* in_sizes, int n_in,
                              void* d_out, int out_size)
{
    const float* x     = (const float*)d_in[0];
    const float* W_in  = (const float*)d_in[1];
    const float* b_in  = (const float*)d_in[2];
    const float* Wq    = (const float*)d_in[3];
    const float* Wk    = (const float*)d_in[4];
    const float* Wv    = (const float*)d_in[5];
    const float* W_out = (const float*)d_in[6];
    const float* b_out = (const float*)d_in[7];
    float* out = (float*)d_out;

    __half *xmid, *xh, *qh, *Wp, *Zp;
    __half2* WC;
    cudaGetSymbolAddress((void**)&xmid, g_xmid);
    cudaGetSymbolAddress((void**)&xh, g_xh);
    cudaGetSymbolAddress((void**)&qh, g_qh);
    cudaGetSymbolAddress((void**)&Wp, g_Wp);
    cudaGetSymbolAddress((void**)&Zp, g_Zp);
    cudaGetSymbolAddress((void**)&WC, g_WC);

    // 0) conversions
    const int n4 = MTOT * DIM / 4;
    f2h_kernel<<<(n4 + 255) / 256, 256>>>((const float4*)x, (uint2*)xh, n4);
    wpair_kernel<<<(DIM * DIM + 255) / 256, 256>>>(W_in, Wp, DIM, DIM);
    wqkv_pair_kernel<<<(32 * 128 + 255) / 256, 256>>>(Wq, Wk, Wv, WC);

    // 1) x_mid = x @ W_in + b_in   (fp16 mma, fp16 output)
    dim3 g1(DIM / 128, MTOT / 128, 1);
    h16gemm_bias_kernel<true><<<g1, 256>>>(xh, (const __half2*)Wp, b_in, xmid, DIM, 0, 0, 0);

    // 2) fused: q-softmax -> g_qh, kv split partials (all fp16 mma)
    dim3 kvGrid(KV_SPLITS, HEADS, BATCH);
    kvq_fused_kernel<<<kvGrid, 128>>>(xmid, WC);

    // 3) kv finalize
    kv_final_kernel<<<(64 * SL * DH + 255) / 256, 256>>>();

    // 4) Z = kv @ W_out -> k-paired fp16
    dim3 zGrid(DIM / 64, HEADS, BATCH);
    zprep_kernel<<<zGrid, 256>>>(W_out);

    // 5) out = Q @ Z_b + b_out   (fp16 mma, K=256, batched; fp32 output)
    dim3 g2(DIM / 128, SEQ / 128, BATCH);
    h16gemm_bias_kernel<false><<<g2, 256>>>(qh, (const __half2*)Zp, b_out, out, QDIM,
                                            (size_t)SEQ * QDIM,
                                            (size_t)QDIM * DIM / 2,
                                            (size_t)SEQ * DIM);
}